// round 16
// baseline (speedup 1.0000x reference)
#include <cuda_runtime.h>
#include <cuda_fp16.h>
#include <cstdint>
#include <cstddef>

// ---------------------------------------------------------------------------
#define BB 8
#define CC 256
#define SS 1024
#define NH 8
#define DK 256
#define HD 2048
#define QKVN 6144

// proj kernel (128x128, 2 CTA/SM) — unchanged from R15
#define BM 128
#define BN 128
#define BKF 32
#define PAD 40
#define TILEB (128 * PAD * 2)
#define STAGEB (2 * TILEB)
#define NSTAGE 5
#define SMEM_DYN (NSTAGE * STAGEB)

// wide kernel (128x256, 64x64 warp tiles, 1 CTA/SM)
#define BNW 256
#define ATILE (128 * PAD * 2)          // 10240
#define BTILE (256 * PAD * 2)          // 20480
#define STGW (ATILE + BTILE)           // 30720
#define NSTW 3
#define SMEM_W (NSTW * STGW)           // 92160
#define SCPW 260                       // fp16 pad for V staging (128 x 260)

typedef __half fp16;

// ---------------------------------------------------------------------------
__device__ __align__(128) fp16 g_xt[BB * SS * CC];
__device__ __align__(128) fp16 g_WpT[QKVN * CC];
__device__ __align__(128) fp16 g_WoT[CC * HD];
__device__ __align__(128) fp16 g_q[BB * NH * SS * DK];    // pre-scaled 1/16
__device__ __align__(128) fp16 g_k[BB * NH * SS * DK];
__device__ __align__(128) fp16 g_v[BB * NH * DK * SS];    // [bh][d][s]
__device__ __align__(128) fp16 g_p[(size_t)BB * NH * SS * SS];
__device__ __align__(128) float g_l[BB * NH * SS];
__device__ __align__(128) fp16 g_ao[BB * SS * HD];

// ---------------------------------------------------------------------------
__device__ __forceinline__ uint32_t smem_u32(const void* p) {
    uint32_t a;
    asm("{ .reg .u64 t; cvta.to.shared.u64 t, %1; cvt.u32.u64 %0, t; }"
        : "=r"(a) : "l"(p));
    return a;
}
__device__ __forceinline__ void cpa16(uint32_t dst, const void* src) {
    asm volatile("cp.async.cg.shared.global [%0], [%1], 16;"
                 :: "r"(dst), "l"(src) : "memory");
}
__device__ __forceinline__ void cpa_commit() {
    asm volatile("cp.async.commit_group;" ::: "memory");
}
template <int N> __device__ __forceinline__ void cpa_wait() {
    asm volatile("cp.async.wait_group %0;" :: "n"(N) : "memory");
}
__device__ __forceinline__ void ldsm4(uint32_t* r, uint32_t addr) {
    asm volatile("ldmatrix.sync.aligned.m8n8.x4.shared.b16 {%0,%1,%2,%3}, [%4];"
                 : "=r"(r[0]), "=r"(r[1]), "=r"(r[2]), "=r"(r[3]) : "r"(addr));
}
__device__ __forceinline__ void mma16816(float* d, const uint32_t* a,
                                         uint32_t b0, uint32_t b1) {
    asm volatile(
        "mma.sync.aligned.m16n8k16.row.col.f32.f16.f16.f32 "
        "{%0,%1,%2,%3}, {%4,%5,%6,%7}, {%8,%9}, {%0,%1,%2,%3};"
        : "+f"(d[0]), "+f"(d[1]), "+f"(d[2]), "+f"(d[3])
        : "r"(a[0]), "r"(a[1]), "r"(a[2]), "r"(a[3]), "r"(b0), "r"(b1));
}

// ---------------------------------------------------------------------------
__global__ __launch_bounds__(256) void convT(const float* __restrict__ in,
                                             fp16* __restrict__ o, int R, int C) {
    __shared__ float t[32][33];
    int z = blockIdx.z;
    const float* I = in + (size_t)z * R * C;
    size_t ob = (size_t)z * R * C;
    int c0 = blockIdx.x * 32, r0 = blockIdx.y * 32;
    int x = threadIdx.x, y = threadIdx.y;
#pragma unroll
    for (int i = 0; i < 32; i += 8)
        t[y + i][x] = I[(size_t)(r0 + y + i) * C + c0 + x];
    __syncthreads();
#pragma unroll
    for (int i = 0; i < 32; i += 8)
        o[ob + (size_t)(c0 + y + i) * R + r0 + x] = __float2half(t[x][y + i]);
}

// ---------------------------------------------------------------------------
// WIDE GEMM: 128x256 CTA tile, 8 warps (2x4), 64x64 warp tile, 3-stage cp.async
// MODE 0: QKV (Q scaled 1/16; V transposed via smem)
// MODE 1: QK^T -> exp fp16 + atomic row sums
// MODE 2: PV -> normalize, fp16 attnout
// ---------------------------------------------------------------------------
template <int MODE>
__global__ __launch_bounds__(256) void gemm_wide(
    const fp16* __restrict__ A, const fp16* __restrict__ B,
    fp16* __restrict__ Cf, int K, int ldA, int ldB, int ldC,
    size_t Az, size_t Bz, size_t Cz,
    const float* __restrict__ bias, float* __restrict__ lsum) {
    extern __shared__ __align__(16) char dynsm[];
    const uint32_t sbase = smem_u32(dynsm);

    const int tid = threadIdx.x;
    const int wid = tid >> 5;
    const int lane = tid & 31;
    const int wr = wid >> 2;   // 0..1 (64-row half)
    const int wc = wid & 3;    // 0..3 (64-col quarter)

    const int z = blockIdx.z;
    const int m0 = blockIdx.y * BM;
    const int n0 = blockIdx.x * BNW;
    const fp16* tA = A + Az * z + (size_t)m0 * ldA;
    const fp16* tB = B + Bz * z + (size_t)n0 * ldB;
    const int NKB = K / BKF;

    // loaders: A 128x32 (2 thr/row, 32B each), B 256x32 (1 thr/row, 64B)
    const int arow = tid >> 1;
    const int acol = (tid & 1) * 16;
    auto issue = [&](int kb, int stg) {
        uint32_t sa = sbase + stg * STGW + (arow * PAD + acol) * 2;
        const fp16* ga = tA + (size_t)arow * ldA + kb * BKF + acol;
        cpa16(sa, ga);
        cpa16(sa + 16, ga + 8);
        uint32_t sb2 = sbase + stg * STGW + ATILE + tid * (PAD * 2);
        const fp16* gb = tB + (size_t)tid * ldB + kb * BKF;
        cpa16(sb2, gb);
        cpa16(sb2 + 16, gb + 8);
        cpa16(sb2 + 32, gb + 16);
        cpa16(sb2 + 48, gb + 24);
    };

    const int lr = lane & 15, lhf = lane >> 4;
    uint32_t aoff[4], boff[4];
#pragma unroll
    for (int im = 0; im < 4; ++im)
        aoff[im] = ((wr * 64 + im * 16 + lr) * PAD + lhf * 8) * 2;
#pragma unroll
    for (int jn = 0; jn < 4; ++jn)
        boff[jn] = ATILE + ((wc * 64 + jn * 16 + lr) * PAD + lhf * 8) * 2;

    float acc[4][8][4] = {};

    issue(0, 0); cpa_commit();
    if (NKB > 1) { issue(1, 1); cpa_commit(); }

    for (int kb = 0; kb < NKB; ++kb) {
        if (kb + 1 < NKB) cpa_wait<1>();
        else cpa_wait<0>();
        __syncthreads();
        if (kb + 2 < NKB) { issue(kb + 2, (kb + 2) % NSTW); cpa_commit(); }

        const int stg = kb % NSTW;
        const uint32_t sA = sbase + stg * STGW;

#pragma unroll
        for (int ks = 0; ks < 2; ++ks) {
            const uint32_t kso = ks * 32;
            uint32_t af[4][4], bf[4][4];
#pragma unroll
            for (int im = 0; im < 4; ++im) ldsm4(af[im], sA + aoff[im] + kso);
#pragma unroll
            for (int jn = 0; jn < 4; ++jn) ldsm4(bf[jn], sA + boff[jn] + kso);
#pragma unroll
            for (int im = 0; im < 4; ++im)
#pragma unroll
                for (int jn = 0; jn < 4; ++jn) {
                    mma16816(acc[im][jn * 2], af[im], bf[jn][0], bf[jn][2]);
                    mma16816(acc[im][jn * 2 + 1], af[im], bf[jn][1], bf[jn][3]);
                }
        }
    }
    __syncthreads();

    const int r0l = lane >> 2;
    const int c0l = (lane & 3) * 2;

    if (MODE == 0) {
        const int hB = n0 / 768;
        const int seg = (n0 % 768) >> 8;      // 256-aligned: full segment per tile
        if (seg < 2) {
            fp16* dst = (seg == 0) ? g_q : g_k;
            const float qs = (seg == 0) ? 0.0625f : 1.0f;
#pragma unroll
            for (int im = 0; im < 4; ++im)
#pragma unroll
                for (int jn = 0; jn < 8; ++jn)
#pragma unroll
                    for (int p = 0; p < 2; ++p) {
                        int m = m0 + wr * 64 + im * 16 + r0l + p * 8;
                        int nb = wc * 64 + jn * 8 + c0l;    // = d (0..255)
                        int b = m >> 10, s2 = m & 1023;
                        size_t row = ((size_t)(b * NH + hB) * SS + s2) * DK + nb;
                        __half2 h;
                        h.x = __float2half((acc[im][jn][p * 2] + bias[n0 + nb]) * qs);
                        h.y = __float2half((acc[im][jn][p * 2 + 1] + bias[n0 + nb + 1]) * qs);
                        *(__half2*)(dst + row) = h;
                    }
        } else {
            // V: stage [m 128][d 256] then write transposed [d][s]
            fp16* sc = (fp16*)dynsm;   // 128 x SCPW = 66.6 KB (fits 92)
#pragma unroll
            for (int im = 0; im < 4; ++im)
#pragma unroll
                for (int jn = 0; jn < 8; ++jn)
#pragma unroll
                    for (int p = 0; p < 2; ++p) {
                        int ml = wr * 64 + im * 16 + r0l + p * 8;
                        int nb = wc * 64 + jn * 8 + c0l;
                        sc[ml * SCPW + nb] =
                            __float2half(acc[im][jn][p * 2] + bias[n0 + nb]);
                        sc[ml * SCPW + nb + 1] =
                            __float2half(acc[im][jn][p * 2 + 1] + bias[n0 + nb + 1]);
                    }
            __syncthreads();
            const int b = m0 >> 10;
            const int s0 = m0 & 1023;
            const int d = tid;                 // 0..255
            fp16* vrow = g_v + ((size_t)(b * NH + hB) * DK + d) * SS + s0;
#pragma unroll
            for (int j = 0; j < 128; j += 2) {
                __half2 h;
                h.x = sc[j * SCPW + d];
                h.y = sc[(j + 1) * SCPW + d];
                *(__half2*)(vrow + j) = h;
            }
        }
    } else if (MODE == 1) {
        fp16* Cb = Cf + Cz * z;
        float rsum[4][2] = {};
#pragma unroll
        for (int im = 0; im < 4; ++im)
#pragma unroll
            for (int p = 0; p < 2; ++p) {
                int m = m0 + wr * 64 + im * 16 + r0l + p * 8;
                float rs = 0.0f;
#pragma unroll
                for (int jn = 0; jn < 8; ++jn) {
                    int nb = wc * 64 + jn * 8 + c0l;
                    float p0 = __expf(acc[im][jn][p * 2]);
                    float p1 = __expf(acc[im][jn][p * 2 + 1]);
                    rs += p0 + p1;
                    __half2 h;
                    h.x = __float2half(p0);
                    h.y = __float2half(p1);
                    *(__half2*)(Cb + (size_t)m * ldC + n0 + nb) = h;
                }
                rsum[im][p] = rs;
            }
#pragma unroll
        for (int im = 0; im < 4; ++im)
#pragma unroll
            for (int p = 0; p < 2; ++p) {
                float s = rsum[im][p];
                s += __shfl_xor_sync(0xffffffffu, s, 1);
                s += __shfl_xor_sync(0xffffffffu, s, 2);
                if ((lane & 3) == 0) {
                    int m = m0 + wr * 64 + im * 16 + r0l + p * 8;
                    atomicAdd(lsum + (size_t)z * SS + m, s);
                }
            }
    } else {  // MODE 2: PV, N=256 (n0=0), normalize
        int b = z >> 3, h2 = z & 7;
        size_t base = (size_t)b * SS * HD + h2 * DK;
        const float* lz = lsum + (size_t)z * SS;
#pragma unroll
        for (int im = 0; im < 4; ++im)
#pragma unroll
            for (int p = 0; p < 2; ++p) {
                int m = m0 + wr * 64 + im * 16 + r0l + p * 8;
                float inv = 1.0f / lz[m];
#pragma unroll
                for (int jn = 0; jn < 8; ++jn) {
                    int nb = wc * 64 + jn * 8 + c0l;
                    size_t idx = base + (size_t)m * HD + n0 + nb;
                    __half2 h;
                    h.x = __float2half(acc[im][jn][p * 2] * inv);
                    h.y = __float2half(acc[im][jn][p * 2 + 1] * inv);
                    *(__half2*)(g_ao + idx) = h;
                }
            }
    }
}

// ---------------------------------------------------------------------------
// PROJ GEMM (R15 MODE 3): 128x128, 2 CTA/SM, 5-stage — unchanged
// ---------------------------------------------------------------------------
__global__ __launch_bounds__(256, 2) void proj_gemm(
    const fp16* __restrict__ A, const fp16* __restrict__ B,
    float* __restrict__ C, int K, int ldA, int ldB,
    const float* __restrict__ bias, const float* __restrict__ resid) {
    extern __shared__ __align__(16) char dynsm[];
    const uint32_t sbase = smem_u32(dynsm);

    const int tid = threadIdx.x;
    const int wid = tid >> 5;
    const int lane = tid & 31;
    const int wr = wid >> 1;
    const int wc = wid & 1;

    const int m0 = blockIdx.y * BM;
    const int n0 = blockIdx.x * BN;
    const fp16* tA = A + (size_t)m0 * ldA;
    const fp16* tB = B + (size_t)n0 * ldB;
    const int NKB = K / BKF;

    const int crow = tid >> 1;
    const int ccol = (tid & 1) * 16;

    auto issueA = [&](int kb, int stg) {
        uint32_t sb = sbase + stg * STAGEB + (crow * PAD + ccol) * 2;
        const fp16* ga = tA + (size_t)crow * ldA + kb * BKF + ccol;
        cpa16(sb, ga);
        cpa16(sb + 16, ga + 8);
    };
    auto issueB = [&](int kb, int stg) {
        uint32_t sb = sbase + stg * STAGEB + TILEB + (crow * PAD + ccol) * 2;
        const fp16* gb = tB + (size_t)crow * ldB + kb * BKF + ccol;
        cpa16(sb, gb);
        cpa16(sb + 16, gb + 8);
    };

    const int lr = lane & 15, lhf = lane >> 4;
    uint32_t aoff[2], boff[4];
#pragma unroll
    for (int im = 0; im < 2; ++im)
        aoff[im] = ((wr * 32 + im * 16 + lr) * PAD + lhf * 8) * 2;
#pragma unroll
    for (int jn = 0; jn < 4; ++jn)
        boff[jn] = ((wc * 64 + jn * 16 + lr) * PAD + lhf * 8) * 2;

    float acc[2][8][4] = {};

#pragma unroll
    for (int s = 0; s < 4; ++s) {
        issueA(s, s); issueB(s, s); cpa_commit();
    }

    for (int kb = 0; kb < NKB; ++kb) {
        if (kb + 4 <= NKB) cpa_wait<3>();
        else if (kb + 3 == NKB) cpa_wait<2>();
        else if (kb + 2 == NKB) cpa_wait<1>();
        else cpa_wait<0>();
        __syncthreads();

        const bool pf = (kb + 4 < NKB);
        const int pstg = (kb + 4) % NSTAGE;
        if (pf) issueA(kb + 4, pstg);

        const int stg = kb % NSTAGE;
        const uint32_t sA = sbase + stg * STAGEB;
        const uint32_t sB = sA + TILEB;

        uint32_t af[2][2][4], bf[2][4][4];
#pragma unroll
        for (int ks = 0; ks < 2; ++ks) {
            const uint32_t kso = ks * 32;
            ldsm4(af[ks][0], sA + aoff[0] + kso);
            ldsm4(af[ks][1], sA + aoff[1] + kso);
#pragma unroll
            for (int jn = 0; jn < 4; ++jn) ldsm4(bf[ks][jn], sB + boff[jn] + kso);
        }
        if (pf) issueB(kb + 4, pstg);

#pragma unroll
        for (int ks = 0; ks < 2; ++ks)
#pragma unroll
            for (int im = 0; im < 2; ++im)
#pragma unroll
                for (int jn = 0; jn < 4; ++jn) {
                    mma16816(acc[im][jn * 2], af[ks][im], bf[ks][jn][0], bf[ks][jn][2]);
                    mma16816(acc[im][jn * 2 + 1], af[ks][im], bf[ks][jn][1], bf[ks][jn][3]);
                }
        if (pf) cpa_commit();
    }
    __syncthreads();

    const int r0l = lane >> 2;
    const int c0l = (lane & 3) * 2;
    float* sc = (float*)dynsm;
    const int bB = m0 >> 10;
    const int s0 = m0 & 1023;
#pragma unroll
    for (int pass = 0; pass < 2; ++pass) {
        __syncthreads();
        if (wc == pass) {
#pragma unroll
            for (int im = 0; im < 2; ++im)
#pragma unroll
                for (int jn = 0; jn < 8; ++jn)
#pragma unroll
                    for (int p = 0; p < 2; ++p) {
                        int rloc = wr * 32 + im * 16 + r0l + p * 8;
                        int cloc = jn * 8 + c0l;
                        sc[rloc * 65 + cloc] = acc[im][jn][p * 2];
                        sc[rloc * 65 + cloc + 1] = acc[im][jn][p * 2 + 1];
                    }
        }
        __syncthreads();
        int nl = tid >> 2;
        int sblk = (tid & 3) * 32;
        int n = n0 + pass * 64 + nl;
        size_t obase = (((size_t)(bB * CC + n)) << 10) + s0 + sblk;
        float bn = bias[n];
#pragma unroll
        for (int j = 0; j < 32; j += 4) {
            float4 xr = *(const float4*)(resid + obase + j);
            float4 o;
            o.x = sc[(sblk + j + 0) * 65 + nl] + bn + xr.x;
            o.y = sc[(sblk + j + 1) * 65 + nl] + bn + xr.y;
            o.z = sc[(sblk + j + 2) * 65 + nl] + bn + xr.z;
            o.w = sc[(sblk + j + 3) * 65 + nl] + bn + xr.w;
            *(float4*)(C + obase + j) = o;
        }
    }
}

// ---------------------------------------------------------------------------
extern "C" void kernel_launch(void* const* d_in, const int* in_sizes, int n_in,
                              void* d_out, int out_size) {
    const float* x  = (const float*)d_in[0];
    const float* Wp = (const float*)d_in[1];
    const float* bp = (const float*)d_in[2];
    const float* Wo = (const float*)d_in[3];
    const float* bo = (const float*)d_in[4];
    float* out = (float*)d_out;

    fp16 *xt, *WpT, *WoT, *q, *k, *v, *pp, *ao;
    float* lp;
    cudaGetSymbolAddress((void**)&xt, g_xt);
    cudaGetSymbolAddress((void**)&WpT, g_WpT);
    cudaGetSymbolAddress((void**)&WoT, g_WoT);
    cudaGetSymbolAddress((void**)&q, g_q);
    cudaGetSymbolAddress((void**)&k, g_k);
    cudaGetSymbolAddress((void**)&v, g_v);
    cudaGetSymbolAddress((void**)&pp, g_p);
    cudaGetSymbolAddress((void**)&ao, g_ao);
    cudaGetSymbolAddress((void**)&lp, g_l);

    cudaFuncSetAttribute(gemm_wide<0>, cudaFuncAttributeMaxDynamicSharedMemorySize, SMEM_W);
    cudaFuncSetAttribute(gemm_wide<1>, cudaFuncAttributeMaxDynamicSharedMemorySize, SMEM_W);
    cudaFuncSetAttribute(gemm_wide<2>, cudaFuncAttributeMaxDynamicSharedMemorySize, SMEM_W);
    cudaFuncSetAttribute(proj_gemm, cudaFuncAttributeMaxDynamicSharedMemorySize, SMEM_DYN);

    cudaMemsetAsync(lp, 0, BB * NH * SS * sizeof(float), 0);

    dim3 tb(32, 8);
    convT<<<dim3(SS / 32, CC / 32, BB), tb>>>(x, xt, CC, SS);
    convT<<<dim3(QKVN / 32, CC / 32, 1), tb>>>(Wp, WpT, CC, QKVN);
    convT<<<dim3(CC / 32, HD / 32, 1), tb>>>(Wo, WoT, HD, CC);

    // QKV projection (wide): [8192,256] @ [6144,256]^T
    gemm_wide<0><<<dim3(QKVN / BNW, (BB * SS) / BM, 1), 256, SMEM_W>>>(
        xt, WpT, nullptr, CC, CC, CC, 0, 0, 0, 0, bp, nullptr);

    // Q K^T -> exp fp16 + row sums (scale folded into Q)
    gemm_wide<1><<<dim3(SS / BNW, SS / BM, BB * NH), 256, SMEM_W>>>(
        q, k, pp, DK, DK, DK, SS,
        (size_t)SS * DK, (size_t)SS * DK, (size_t)SS * SS, nullptr, lp);

    // P~ V -> normalized attnout
    gemm_wide<2><<<dim3(DK / BNW, SS / BM, BB * NH), 256, SMEM_W>>>(
        pp, v, nullptr, SS, SS, SS, 0,
        (size_t)SS * SS, (size_t)DK * SS, 0, nullptr, lp);

    // Out projection + bias + residual
    proj_gemm<<<dim3(CC / BN, (BB * SS) / BM), 256, SMEM_DYN>>>(
        ao, WoT, out, HD, HD, HD, bo, x);
}

// round 17
// speedup vs baseline: 1.3158x; 1.3158x over previous
#include <cuda_runtime.h>
#include <cuda_fp16.h>
#include <cstdint>
#include <cstddef>

// ---------------------------------------------------------------------------
#define BB 8
#define CC 256
#define SS 1024
#define NH 8
#define DK 256
#define HD 2048
#define QKVN 6144

#define BM 128
#define BN 128
#define BKF 32                     // K elements per block
#define PAD 40                     // fp16 per smem row (80B; ldsm conflict-free)
#define TILEB (128 * PAD * 2)      // 10240 B per tile
#define STAGEB (2 * TILEB)         // A, B
#define NSTAGE 5
#define SMEM_DYN (NSTAGE * STAGEB) // 102400 B (2 CTAs/SM)
#define SCP 132                    // fp16 pad for V-transpose staging

// proj kernel: BN=64 for 256-CTA fill
#define BNP 64
#define ATILEP (128 * PAD * 2)     // 10240
#define BTILEP (64 * PAD * 2)      // 5120
#define STGP (ATILEP + BTILEP)     // 15360
#define SMEM_P (NSTAGE * STGP)     // 76800 (2 CTAs/SM)

typedef __half fp16;

// ---------------------------------------------------------------------------
// Device scratch (allocation-free)
// ---------------------------------------------------------------------------
__device__ __align__(128) fp16 g_xt[BB * SS * CC];        // [b*S+s][c]
__device__ __align__(128) fp16 g_WpT[QKVN * CC];          // [n][k]
__device__ __align__(128) fp16 g_WoT[CC * HD];            // [n][k]
__device__ __align__(128) fp16 g_q[BB * NH * SS * DK];    // [bh][s][d] (pre-scaled 1/16)
__device__ __align__(128) fp16 g_k[BB * NH * SS * DK];    // [bh][s][d]
__device__ __align__(128) fp16 g_v[BB * NH * DK * SS];    // [bh][d][s]  TRANSPOSED
__device__ __align__(128) fp16 g_p[(size_t)BB * NH * SS * SS]; // unnormalized exp
__device__ __align__(128) float g_l[BB * NH * SS];        // row sums of exp
__device__ __align__(128) fp16 g_ao[BB * SS * HD];        // [b*S+s][h*DK+d]

// ---------------------------------------------------------------------------
// PTX helpers
// ---------------------------------------------------------------------------
__device__ __forceinline__ uint32_t smem_u32(const void* p) {
    uint32_t a;
    asm("{ .reg .u64 t; cvta.to.shared.u64 t, %1; cvt.u32.u64 %0, t; }"
        : "=r"(a) : "l"(p));
    return a;
}
__device__ __forceinline__ void cpa16(uint32_t dst, const void* src) {
    asm volatile("cp.async.cg.shared.global [%0], [%1], 16;"
                 :: "r"(dst), "l"(src) : "memory");
}
__device__ __forceinline__ void cpa_commit() {
    asm volatile("cp.async.commit_group;" ::: "memory");
}
template <int N> __device__ __forceinline__ void cpa_wait() {
    asm volatile("cp.async.wait_group %0;" :: "n"(N) : "memory");
}
__device__ __forceinline__ void ldsm4(uint32_t* r, uint32_t addr) {
    asm volatile("ldmatrix.sync.aligned.m8n8.x4.shared.b16 {%0,%1,%2,%3}, [%4];"
                 : "=r"(r[0]), "=r"(r[1]), "=r"(r[2]), "=r"(r[3]) : "r"(addr));
}
__device__ __forceinline__ void mma16816(float* d, const uint32_t* a,
                                         uint32_t b0, uint32_t b1) {
    asm volatile(
        "mma.sync.aligned.m16n8k16.row.col.f32.f16.f16.f32 "
        "{%0,%1,%2,%3}, {%4,%5,%6,%7}, {%8,%9}, {%0,%1,%2,%3};"
        : "+f"(d[0]), "+f"(d[1]), "+f"(d[2]), "+f"(d[3])
        : "r"(a[0]), "r"(a[1]), "r"(a[2]), "r"(a[3]), "r"(b0), "r"(b1));
}

// ---------------------------------------------------------------------------
// fp32 [Z][R][C] -> transposed fp16 [Z][C][R]
// ---------------------------------------------------------------------------
__global__ __launch_bounds__(256) void convT(const float* __restrict__ in,
                                             fp16* __restrict__ o, int R, int C) {
    __shared__ float t[32][33];
    int z = blockIdx.z;
    const float* I = in + (size_t)z * R * C;
    size_t ob = (size_t)z * R * C;
    int c0 = blockIdx.x * 32, r0 = blockIdx.y * 32;
    int x = threadIdx.x, y = threadIdx.y;
#pragma unroll
    for (int i = 0; i < 32; i += 8)
        t[y + i][x] = I[(size_t)(r0 + y + i) * C + c0 + x];
    __syncthreads();
#pragma unroll
    for (int i = 0; i < 32; i += 8)
        o[ob + (size_t)(c0 + y + i) * R + r0 + x] = __float2half(t[x][y + i]);
}

// ---------------------------------------------------------------------------
// fp16 GEMM (R15): 5-stage cp.async, split A/B issue, 1 sync/iter.
// MODE 0: QKV -> bias; Q scaled 1/16; K; V transposed via smem staging
// MODE 1: QK^T -> P~ = exp(s) fp16 + atomic row sums into lsum
// MODE 2: PV -> normalize by 1/lsum[row], fp16 attnout
// ---------------------------------------------------------------------------
template <int MODE>
__global__ __launch_bounds__(256, 2) void gemm_fp16(
    const fp16* __restrict__ A, const fp16* __restrict__ B,
    fp16* __restrict__ Cf, int K, int ldA, int ldB, int ldC,
    size_t Az, size_t Bz, size_t Cz,
    const float* __restrict__ bias, float* __restrict__ lsum) {
    extern __shared__ __align__(16) char dynsm[];
    const uint32_t sbase = smem_u32(dynsm);

    const int tid = threadIdx.x;
    const int wid = tid >> 5;
    const int lane = tid & 31;
    const int wr = wid >> 1;
    const int wc = wid & 1;

    const int z = blockIdx.z;
    const int m0 = blockIdx.y * BM;
    const int n0 = blockIdx.x * BN;
    const fp16* tA = A + Az * z + (size_t)m0 * ldA;
    const fp16* tB = B + Bz * z + (size_t)n0 * ldB;
    const int NKB = K / BKF;

    const int crow = tid >> 1;
    const int ccol = (tid & 1) * 16;

    auto issueA = [&](int kb, int stg) {
        uint32_t sb = sbase + stg * STAGEB + (crow * PAD + ccol) * 2;
        const fp16* ga = tA + (size_t)crow * ldA + kb * BKF + ccol;
        cpa16(sb, ga);
        cpa16(sb + 16, ga + 8);
    };
    auto issueB = [&](int kb, int stg) {
        uint32_t sb = sbase + stg * STAGEB + TILEB + (crow * PAD + ccol) * 2;
        const fp16* gb = tB + (size_t)crow * ldB + kb * BKF + ccol;
        cpa16(sb, gb);
        cpa16(sb + 16, gb + 8);
    };

    const int lr = lane & 15, lhf = lane >> 4;
    uint32_t aoff[2], boff[4];
#pragma unroll
    for (int im = 0; im < 2; ++im)
        aoff[im] = ((wr * 32 + im * 16 + lr) * PAD + lhf * 8) * 2;
#pragma unroll
    for (int jn = 0; jn < 4; ++jn)
        boff[jn] = ((wc * 64 + jn * 16 + lr) * PAD + lhf * 8) * 2;

    float acc[2][8][4] = {};

#pragma unroll
    for (int s = 0; s < 4; ++s) {
        issueA(s, s); issueB(s, s); cpa_commit();
    }

    for (int kb = 0; kb < NKB; ++kb) {
        if (kb + 4 <= NKB) cpa_wait<3>();
        else if (kb + 3 == NKB) cpa_wait<2>();
        else if (kb + 2 == NKB) cpa_wait<1>();
        else cpa_wait<0>();
        __syncthreads();

        const bool pf = (kb + 4 < NKB);
        const int pstg = (kb + 4) % NSTAGE;
        if (pf) issueA(kb + 4, pstg);

        const int stg = kb % NSTAGE;
        const uint32_t sA = sbase + stg * STAGEB;
        const uint32_t sB = sA + TILEB;

        uint32_t af[2][2][4], bf[2][4][4];
#pragma unroll
        for (int ks = 0; ks < 2; ++ks) {
            const uint32_t kso = ks * 32;
            ldsm4(af[ks][0], sA + aoff[0] + kso);
            ldsm4(af[ks][1], sA + aoff[1] + kso);
#pragma unroll
            for (int jn = 0; jn < 4; ++jn) ldsm4(bf[ks][jn], sB + boff[jn] + kso);
        }
        if (pf) issueB(kb + 4, pstg);

#pragma unroll
        for (int ks = 0; ks < 2; ++ks)
#pragma unroll
            for (int im = 0; im < 2; ++im)
#pragma unroll
                for (int jn = 0; jn < 4; ++jn) {
                    mma16816(acc[im][jn * 2], af[ks][im], bf[ks][jn][0], bf[ks][jn][2]);
                    mma16816(acc[im][jn * 2 + 1], af[ks][im], bf[ks][jn][1], bf[ks][jn][3]);
                }
        if (pf) cpa_commit();
    }
    __syncthreads();

    const int r0l = lane >> 2;
    const int c0l = (lane & 3) * 2;

    if (MODE == 0) {
        const int hB = n0 / 768;
        const int loc0 = n0 % 768;
        const int seg = loc0 >> 8;
        const int d0 = loc0 & 255;
        if (seg < 2) {
            fp16* dst = (seg == 0) ? g_q : g_k;
            const float qs = (seg == 0) ? 0.0625f : 1.0f;
#pragma unroll
            for (int im = 0; im < 2; ++im)
#pragma unroll
                for (int jn = 0; jn < 8; ++jn)
#pragma unroll
                    for (int p = 0; p < 2; ++p) {
                        int m = m0 + wr * 32 + im * 16 + r0l + p * 8;
                        int nb = wc * 64 + jn * 8 + c0l;
                        int b = m >> 10, s2 = m & 1023;
                        size_t row = ((size_t)(b * NH + hB) * SS + s2) * DK + d0 + nb;
                        __half2 h;
                        h.x = __float2half((acc[im][jn][p * 2] + bias[n0 + nb]) * qs);
                        h.y = __float2half((acc[im][jn][p * 2 + 1] + bias[n0 + nb + 1]) * qs);
                        *(__half2*)(dst + row) = h;
                    }
        } else {
            fp16* sc = (fp16*)dynsm;
#pragma unroll
            for (int im = 0; im < 2; ++im)
#pragma unroll
                for (int jn = 0; jn < 8; ++jn)
#pragma unroll
                    for (int p = 0; p < 2; ++p) {
                        int ml = wr * 32 + im * 16 + r0l + p * 8;
                        int nb = wc * 64 + jn * 8 + c0l;
                        sc[ml * SCP + nb] =
                            __float2half(acc[im][jn][p * 2] + bias[n0 + nb]);
                        sc[ml * SCP + nb + 1] =
                            __float2half(acc[im][jn][p * 2 + 1] + bias[n0 + nb + 1]);
                    }
            __syncthreads();
            const int b = m0 >> 10;
            const int s0 = m0 & 1023;
            const int d = tid & 127;
            const int mh = (tid >> 7) * 64;
            fp16* vrow = g_v + ((size_t)(b * NH + hB) * DK + d0 + d) * SS + s0 + mh;
#pragma unroll
            for (int j = 0; j < 64; j += 2) {
                __half2 h;
                h.x = sc[(mh + j) * SCP + d];
                h.y = sc[(mh + j + 1) * SCP + d];
                *(__half2*)(vrow + j) = h;
            }
        }
    } else if (MODE == 1) {
        fp16* Cb = Cf + Cz * z;
        float rsum[2][2] = {};
#pragma unroll
        for (int im = 0; im < 2; ++im)
#pragma unroll
            for (int p = 0; p < 2; ++p) {
                int m = m0 + wr * 32 + im * 16 + r0l + p * 8;
                float rs = 0.0f;
#pragma unroll
                for (int jn = 0; jn < 8; ++jn) {
                    int nb = wc * 64 + jn * 8 + c0l;
                    float p0 = __expf(acc[im][jn][p * 2]);
                    float p1 = __expf(acc[im][jn][p * 2 + 1]);
                    rs += p0 + p1;
                    __half2 h;
                    h.x = __float2half(p0);
                    h.y = __float2half(p1);
                    *(__half2*)(Cb + (size_t)m * ldC + n0 + nb) = h;
                }
                rsum[im][p] = rs;
            }
#pragma unroll
        for (int im = 0; im < 2; ++im)
#pragma unroll
            for (int p = 0; p < 2; ++p) {
                float s = rsum[im][p];
                s += __shfl_xor_sync(0xffffffffu, s, 1);
                s += __shfl_xor_sync(0xffffffffu, s, 2);
                if ((lane & 3) == 0) {
                    int m = m0 + wr * 32 + im * 16 + r0l + p * 8;
                    atomicAdd(lsum + (size_t)z * SS + m, s);
                }
            }
    } else {  // MODE 2
        int b = z >> 3, h2 = z & 7;
        size_t base = (size_t)b * SS * HD + h2 * DK;
        const float* lz = lsum + (size_t)z * SS;
#pragma unroll
        for (int im = 0; im < 2; ++im)
#pragma unroll
            for (int p = 0; p < 2; ++p) {
                int m = m0 + wr * 32 + im * 16 + r0l + p * 8;
                float inv = 1.0f / lz[m];
#pragma unroll
                for (int jn = 0; jn < 8; ++jn) {
                    int nb = wc * 64 + jn * 8 + c0l;
                    size_t idx = base + (size_t)m * HD + n0 + nb;
                    __half2 h;
                    h.x = __float2half(acc[im][jn][p * 2] * inv);
                    h.y = __float2half(acc[im][jn][p * 2 + 1] * inv);
                    *(__half2*)(g_ao + idx) = h;
                }
            }
    }
}

// ---------------------------------------------------------------------------
// PROJ: 128x64 tile (grid 4x64 = 256 CTAs, ~86% fill), same 5-stage recipe.
// 8 warps as 4x2, warp tile 32x32. Epilogue: smem transpose + bias + resid.
// ---------------------------------------------------------------------------
__global__ __launch_bounds__(256, 2) void proj_gemm(
    const fp16* __restrict__ A, const fp16* __restrict__ B,
    float* __restrict__ C, int K, int ldA, int ldB,
    const float* __restrict__ bias, const float* __restrict__ resid) {
    extern __shared__ __align__(16) char dynsm[];
    const uint32_t sbase = smem_u32(dynsm);

    const int tid = threadIdx.x;
    const int wid = tid >> 5;
    const int lane = tid & 31;
    const int wr = wid >> 1;   // 0..3 (32-row band)
    const int wc = wid & 1;    // 0..1 (32-col band)

    const int m0 = blockIdx.y * BM;
    const int n0 = blockIdx.x * BNP;
    const fp16* tA = A + (size_t)m0 * ldA;
    const fp16* tB = B + (size_t)n0 * ldB;
    const int NKB = K / BKF;

    // A: 128 rows, 2 thr/row; B: 64 rows, 4 thr/row (8 elems = 16B each)
    const int arow = tid >> 1;
    const int acol = (tid & 1) * 16;
    const int brow = tid >> 2;
    const int bcol = (tid & 3) * 8;

    auto issueA = [&](int kb, int stg) {
        uint32_t sb = sbase + stg * STGP + (arow * PAD + acol) * 2;
        const fp16* ga = tA + (size_t)arow * ldA + kb * BKF + acol;
        cpa16(sb, ga);
        cpa16(sb + 16, ga + 8);
    };
    auto issueB = [&](int kb, int stg) {
        uint32_t sb = sbase + stg * STGP + ATILEP + (brow * PAD + bcol) * 2;
        const fp16* gb = tB + (size_t)brow * ldB + kb * BKF + bcol;
        cpa16(sb, gb);
    };

    const int lr = lane & 15, lhf = lane >> 4;
    uint32_t aoff[2], boff[2];
#pragma unroll
    for (int im = 0; im < 2; ++im)
        aoff[im] = ((wr * 32 + im * 16 + lr) * PAD + lhf * 8) * 2;
#pragma unroll
    for (int j4 = 0; j4 < 2; ++j4)
        boff[j4] = ATILEP + ((wc * 32 + j4 * 16 + lr) * PAD + lhf * 8) * 2;

    float acc[2][4][4] = {};

#pragma unroll
    for (int s = 0; s < 4; ++s) {
        issueA(s, s); issueB(s, s); cpa_commit();
    }

    for (int kb = 0; kb < NKB; ++kb) {
        if (kb + 4 <= NKB) cpa_wait<3>();
        else if (kb + 3 == NKB) cpa_wait<2>();
        else if (kb + 2 == NKB) cpa_wait<1>();
        else cpa_wait<0>();
        __syncthreads();

        const bool pf = (kb + 4 < NKB);
        const int pstg = (kb + 4) % NSTAGE;
        if (pf) issueA(kb + 4, pstg);

        const int stg = kb % NSTAGE;
        const uint32_t sA = sbase + stg * STGP;

        uint32_t af[2][2][4], bf[2][2][4];
#pragma unroll
        for (int ks = 0; ks < 2; ++ks) {
            const uint32_t kso = ks * 32;
            ldsm4(af[ks][0], sA + aoff[0] + kso);
            ldsm4(af[ks][1], sA + aoff[1] + kso);
            ldsm4(bf[ks][0], sA + boff[0] + kso);
            ldsm4(bf[ks][1], sA + boff[1] + kso);
        }
        if (pf) issueB(kb + 4, pstg);

#pragma unroll
        for (int ks = 0; ks < 2; ++ks)
#pragma unroll
            for (int im = 0; im < 2; ++im)
#pragma unroll
                for (int j4 = 0; j4 < 2; ++j4) {
                    mma16816(acc[im][j4 * 2], af[ks][im], bf[ks][j4][0], bf[ks][j4][2]);
                    mma16816(acc[im][j4 * 2 + 1], af[ks][im], bf[ks][j4][1], bf[ks][j4][3]);
                }
        if (pf) cpa_commit();
    }
    __syncthreads();

    // epilogue: single-phase smem transpose (128 x 68 fp32 = 34.8 KB < 76.8 KB)
    const int r0l = lane >> 2;
    const int c0l = (lane & 3) * 2;
    float* sc = (float*)dynsm;
    const int bB = m0 >> 10;
    const int s0 = m0 & 1023;
#pragma unroll
    for (int im = 0; im < 2; ++im)
#pragma unroll
        for (int jn = 0; jn < 4; ++jn)
#pragma unroll
            for (int p = 0; p < 2; ++p) {
                int rloc = wr * 32 + im * 16 + r0l + p * 8;
                int cloc = wc * 32 + jn * 8 + c0l;
                sc[rloc * 68 + cloc] = acc[im][jn][p * 2];
                sc[rloc * 68 + cloc + 1] = acc[im][jn][p * 2 + 1];
            }
    __syncthreads();
    int nl = tid >> 2;              // 0..63 (n within tile)
    int sblk = (tid & 3) * 32;      // m sub-block
    int n = n0 + nl;
    size_t obase = (((size_t)(bB * CC + n)) << 10) + s0 + sblk;
    float bn = bias[n];
#pragma unroll
    for (int j = 0; j < 32; j += 4) {
        float4 xr = *(const float4*)(resid + obase + j);
        float4 o;
        o.x = sc[(sblk + j + 0) * 68 + nl] + bn + xr.x;
        o.y = sc[(sblk + j + 1) * 68 + nl] + bn + xr.y;
        o.z = sc[(sblk + j + 2) * 68 + nl] + bn + xr.z;
        o.w = sc[(sblk + j + 3) * 68 + nl] + bn + xr.w;
        *(float4*)(C + obase + j) = o;
    }
}

// ---------------------------------------------------------------------------
extern "C" void kernel_launch(void* const* d_in, const int* in_sizes, int n_in,
                              void* d_out, int out_size) {
    const float* x  = (const float*)d_in[0];
    const float* Wp = (const float*)d_in[1];
    const float* bp = (const float*)d_in[2];
    const float* Wo = (const float*)d_in[3];
    const float* bo = (const float*)d_in[4];
    float* out = (float*)d_out;

    fp16 *xt, *WpT, *WoT, *q, *k, *v, *pp, *ao;
    float* lp;
    cudaGetSymbolAddress((void**)&xt, g_xt);
    cudaGetSymbolAddress((void**)&WpT, g_WpT);
    cudaGetSymbolAddress((void**)&WoT, g_WoT);
    cudaGetSymbolAddress((void**)&q, g_q);
    cudaGetSymbolAddress((void**)&k, g_k);
    cudaGetSymbolAddress((void**)&v, g_v);
    cudaGetSymbolAddress((void**)&pp, g_p);
    cudaGetSymbolAddress((void**)&ao, g_ao);
    cudaGetSymbolAddress((void**)&lp, g_l);

    cudaFuncSetAttribute(gemm_fp16<0>, cudaFuncAttributeMaxDynamicSharedMemorySize, SMEM_DYN);
    cudaFuncSetAttribute(gemm_fp16<1>, cudaFuncAttributeMaxDynamicSharedMemorySize, SMEM_DYN);
    cudaFuncSetAttribute(gemm_fp16<2>, cudaFuncAttributeMaxDynamicSharedMemorySize, SMEM_DYN);
    cudaFuncSetAttribute(proj_gemm, cudaFuncAttributeMaxDynamicSharedMemorySize, SMEM_P);

    cudaMemsetAsync(lp, 0, BB * NH * SS * sizeof(float), 0);

    dim3 tb(32, 8);
    convT<<<dim3(SS / 32, CC / 32, BB), tb>>>(x, xt, CC, SS);
    convT<<<dim3(QKVN / 32, CC / 32, 1), tb>>>(Wp, WpT, CC, QKVN);
    convT<<<dim3(CC / 32, HD / 32, 1), tb>>>(Wo, WoT, HD, CC);

    // QKV projection: [8192,256] @ [6144,256]^T  (Q pre-scaled, V transposed)
    gemm_fp16<0><<<dim3(QKVN / BN, (BB * SS) / BM, 1), 256, SMEM_DYN>>>(
        xt, WpT, nullptr, CC, CC, CC, 0, 0, 0, 0, bp, nullptr);

    // Q K^T -> P~ = exp(s) fp16 + row sums
    gemm_fp16<1><<<dim3(SS / BN, SS / BM, BB * NH), 256, SMEM_DYN>>>(
        q, k, pp, DK, DK, DK, SS,
        (size_t)SS * DK, (size_t)SS * DK, (size_t)SS * SS, nullptr, lp);

    // P~ V -> normalized attnout
    gemm_fp16<2><<<dim3(DK / BN, SS / BM, BB * NH), 256, SMEM_DYN>>>(
        pp, v, nullptr, SS, SS, SS, 0,
        (size_t)SS * SS, (size_t)DK * SS, 0, nullptr, lp);

    // Out projection + bias + residual (128x64 tiles, 256 CTAs)
    proj_gemm<<<dim3(CC / BNP, (BB * SS) / BM), 256, SMEM_P>>>(
        ao, WoT, out, HD, HD, HD, bo, x);
}